// round 15
// baseline (speedup 1.0000x reference)
#include <cuda_runtime.h>
#include <cuda_bf16.h>
#include <cstdint>

#define DDIM    4096
#define SEQ     512
#define SPLIT   32
#define SCALE   2.0f
#define MT      64       // tokens per block
#define NB      128      // d per block
#define THREADS 256
#define TRS     160      // transpose-tile row stride in bytes (40 floats)
#define TWB     2560     // per-warp transpose tile bytes (16 rows x TRS)

__device__ __forceinline__ uint32_t cvta_s(const void* p) {
    return (uint32_t)__cvta_generic_to_shared(p);
}
__device__ __forceinline__ uint32_t bf2(float a, float b) {
    __nv_bfloat162 t = __floats2bfloat162_rn(a, b);
    return *reinterpret_cast<uint32_t*>(&t);
}
__device__ __forceinline__ void ldsm_x4(uint32_t& r0, uint32_t& r1, uint32_t& r2,
                                        uint32_t& r3, uint32_t addr) {
    asm volatile("ldmatrix.sync.aligned.m8n8.x4.shared.b16 {%0,%1,%2,%3}, [%4];"
                 : "=r"(r0), "=r"(r1), "=r"(r2), "=r"(r3) : "r"(addr));
}
__device__ __forceinline__ void ldsm_x2(uint32_t& r0, uint32_t& r1, uint32_t addr) {
    asm volatile("ldmatrix.sync.aligned.m8n8.x2.shared.b16 {%0,%1}, [%2];"
                 : "=r"(r0), "=r"(r1) : "r"(addr));
}
__device__ __forceinline__ void mma16816(float* d, const uint32_t* a, const uint32_t* b) {
    asm volatile(
        "mma.sync.aligned.m16n8k16.row.col.f32.bf16.bf16.f32 "
        "{%0,%1,%2,%3}, {%4,%5,%6,%7}, {%8,%9}, {%0,%1,%2,%3};"
        : "+f"(d[0]), "+f"(d[1]), "+f"(d[2]), "+f"(d[3])
        : "r"(a[0]), "r"(a[1]), "r"(a[2]), "r"(a[3]), "r"(b[0]), "r"(b[1]));
}

// ===== fused: router + coef gather + mma.sync delta GEMM + transpose epilogue =====
__global__ __launch_bounds__(THREADS, 3)
void moe_emb_mma(const int* __restrict__ xg,
                 const float* __restrict__ emb,
                 const float* __restrict__ A1, const float* __restrict__ B1,
                 const float* __restrict__ A2, const float* __restrict__ B2,
                 const float* __restrict__ WrI, const float* __restrict__ brI,
                 const float* __restrict__ WrT, const float* __restrict__ brT,
                 float* __restrict__ out, int V, int n_tok)
{
    // phase A: A tile @0 (64x80B = 5120), B tile @5120 (128x80B = 10240)
    // phase B: per-warp 16x160B transpose tiles (8 x 2560 = 20480)
    __shared__ __align__(16) char sm[20480];
    __shared__ int   sx[MT];
    __shared__ float sw[MT * 2];

    const int tid  = threadIdx.x;
    const int lane = tid & 31;
    const int w    = tid >> 5;
    const int t0   = blockIdx.y * MT;
    const int d0   = blockIdx.x * NB;

    char* smA = sm;
    char* smB = sm + 5120;

    // ---- phase 0: per-token index + router weights ----
    if (tid < MT) {
        int tg = t0 + tid;
        int tr = (tg < n_tok) ? tg : (n_tok - 1);
        int xi = xg[tr];
        xi = (xi < 0) ? 0 : ((xi >= V) ? V - 1 : xi);
        sx[tid] = xi;
        bool img = ((tg % SEQ) < SPLIT);
        const float* Wr = img ? WrI : WrT;
        const float* br = img ? brI : brT;
        float l0 = __ldg(Wr + xi) + __ldg(br + 0);
        float l1 = __ldg(Wr + (size_t)V + xi) + __ldg(br + 1);
        float w0 = 1.0f / (1.0f + __expf(l1 - l0));
        sw[2 * tid]     = w0 * SCALE;
        sw[2 * tid + 1] = (1.0f - w0) * SCALE;
    }
    // ---- stage B tile: row n = [B1[d0+n][0..15] | B2[d0+n][0..15]] as bf16 ----
    {
        int n = tid >> 1, hb = tid & 1;
        const float* src = hb ? B2 : B1;
        const float4* s4 = reinterpret_cast<const float4*>(src + (size_t)(d0 + n) * 16);
        float4 v0 = s4[0], v1 = s4[1], v2 = s4[2], v3 = s4[3];
        uint4 p0, p1;
        p0.x = bf2(v0.x, v0.y); p0.y = bf2(v0.z, v0.w);
        p0.z = bf2(v1.x, v1.y); p0.w = bf2(v1.z, v1.w);
        p1.x = bf2(v2.x, v2.y); p1.y = bf2(v2.z, v2.w);
        p1.z = bf2(v3.x, v3.y); p1.w = bf2(v3.z, v3.w);
        char* dst = smB + n * 80 + hb * 32;
        *reinterpret_cast<uint4*>(dst)      = p0;
        *reinterpret_cast<uint4*>(dst + 16) = p1;
    }
    __syncthreads();

    // ---- phase 1: coef gather -> A tile. thread covers (t = tid>>2, j = (tid&3)*8 .. +7) ----
    {
        int t = tid >> 2, c = tid & 3;
        int xi = sx[t];
        const float* A = (c < 2) ? A1 : A2;
        float wgt = (c < 2) ? sw[2 * t] : sw[2 * t + 1];
        int jb = (c & 1) * 8;
        float v[8];
#pragma unroll
        for (int q = 0; q < 8; ++q)
            v[q] = wgt * __ldg(A + (size_t)(jb + q) * V + xi);
        uint4 pv;
        pv.x = bf2(v[0], v[1]); pv.y = bf2(v[2], v[3]);
        pv.z = bf2(v[4], v[5]); pv.w = bf2(v[6], v[7]);
        *reinterpret_cast<uint4*>(smA + t * 80 + c * 16) = pv;
    }
    __syncthreads();

    const uint32_t sAu = cvta_s(smA), sBu = cvta_s(smB);
    const int tgw = (w >> 2) * 32;     // warp token group (0/32)
    const int dw  = (w & 3) * 32;      // warp d group within block

    // ---- B fragments ----
    uint32_t bfr[4][2][2];
#pragma unroll
    for (int ni = 0; ni < 4; ++ni)
#pragma unroll
        for (int kt = 0; kt < 2; ++kt) {
            uint32_t addr = sBu + (uint32_t)(dw + ni * 8 + (lane & 7)) * 80
                          + (uint32_t)(kt * 16 + ((lane >> 3) & 1) * 8) * 2;
            ldsm_x2(bfr[ni][kt][0], bfr[ni][kt][1], addr);
        }
    // ---- A fragments, both m-halves ----
    const int asel = lane >> 3;
    const int arow_off = (asel & 1) * 8 + (lane & 7);
    const int acol_off = (asel >> 1) * 8;
    uint32_t a0[2][4], a1[2][4];
#pragma unroll
    for (int kt = 0; kt < 2; ++kt) {
        ldsm_x4(a0[kt][0], a0[kt][1], a0[kt][2], a0[kt][3],
                sAu + (uint32_t)(tgw + arow_off) * 80
                    + (uint32_t)(kt * 16 + acol_off) * 2);
        ldsm_x4(a1[kt][0], a1[kt][1], a1[kt][2], a1[kt][3],
                sAu + (uint32_t)(tgw + 16 + arow_off) * 80
                    + (uint32_t)(kt * 16 + acol_off) * 2);
    }

    const int brow = lane >> 3;          // 0..3
    const int dq   = lane & 7;           // 0..7
    const int dgl  = d0 + dw + dq * 4;   // this lane's global d

    // ---- half-0 base gathers (4 x LDG.128, streaming) ----
    float4 bs0[4];
#pragma unroll
    for (int it = 0; it < 4; ++it)
        bs0[it] = __ldcs(reinterpret_cast<const float4*>(
            emb + (size_t)sx[tgw + it * 4 + brow] * DDIM + dgl));

    __syncthreads();   // A/B tiles consumed; smem becomes transpose buffers
    char* tw = sm + w * TWB;             // 16 rows x TRS bytes

    const int srow  = lane >> 2;         // frag row 0..7
    const int scol2 = 2 * (lane & 3);

    // ================= half 0 (tokens tgw+0..15) =================
    {
        float acc[4][4];
#pragma unroll
        for (int ni = 0; ni < 4; ++ni) { acc[ni][0]=acc[ni][1]=acc[ni][2]=acc[ni][3]=0.f; }
#pragma unroll
        for (int kt = 0; kt < 2; ++kt)
#pragma unroll
            for (int ni = 0; ni < 4; ++ni)
                mma16816(acc[ni], a0[kt], bfr[ni][kt]);

        // prefetch half-1 base gathers while MMA results settle
        float4 bs1[4];
#pragma unroll
        for (int it = 0; it < 4; ++it)
            bs1[it] = __ldcs(reinterpret_cast<const float4*>(
                emb + (size_t)sx[tgw + 16 + it * 4 + brow] * DDIM + dgl));

#pragma unroll
        for (int ni = 0; ni < 4; ++ni)
#pragma unroll
            for (int h = 0; h < 2; ++h)
                *reinterpret_cast<float2*>(tw + (h * 8 + srow) * TRS
                                              + (ni * 8 + scol2) * 4) =
                    make_float2(acc[ni][2 * h], acc[ni][2 * h + 1]);
        __syncwarp();

#pragma unroll
        for (int it = 0; it < 4; ++it) {
            int rt = it * 4 + brow;
            float4 dl = *reinterpret_cast<const float4*>(tw + rt * TRS + dq * 16);
            float4 o = bs0[it];
            o.x += dl.x; o.y += dl.y; o.z += dl.z; o.w += dl.w;
            int tk = tgw + rt;
            if (t0 + tk < n_tok)
                __stcs(reinterpret_cast<float4*>(out + (size_t)(t0 + tk) * DDIM + dgl), o);
        }
        __syncwarp();

        // ================= half 1 (tokens tgw+16..31) =================
        float acc1[4][4];
#pragma unroll
        for (int ni = 0; ni < 4; ++ni) { acc1[ni][0]=acc1[ni][1]=acc1[ni][2]=acc1[ni][3]=0.f; }
#pragma unroll
        for (int kt = 0; kt < 2; ++kt)
#pragma unroll
            for (int ni = 0; ni < 4; ++ni)
                mma16816(acc1[ni], a1[kt], bfr[ni][kt]);

#pragma unroll
        for (int ni = 0; ni < 4; ++ni)
#pragma unroll
            for (int h = 0; h < 2; ++h)
                *reinterpret_cast<float2*>(tw + (h * 8 + srow) * TRS
                                              + (ni * 8 + scol2) * 4) =
                    make_float2(acc1[ni][2 * h], acc1[ni][2 * h + 1]);
        __syncwarp();

#pragma unroll
        for (int it = 0; it < 4; ++it) {
            int rt = it * 4 + brow;
            float4 dl = *reinterpret_cast<const float4*>(tw + rt * TRS + dq * 16);
            float4 o = bs1[it];
            o.x += dl.x; o.y += dl.y; o.z += dl.z; o.w += dl.w;
            int tk = tgw + 16 + rt;
            if (t0 + tk < n_tok)
                __stcs(reinterpret_cast<float4*>(out + (size_t)(t0 + tk) * DDIM + dgl), o);
        }
    }
}

extern "C" void kernel_launch(void* const* d_in, const int* in_sizes, int n_in,
                              void* d_out, int out_size) {
    const int*   x   = (const int*)d_in[0];
    const float* emb = (const float*)d_in[1];
    const float* A1  = (const float*)d_in[2];
    const float* B1  = (const float*)d_in[3];
    const float* A2  = (const float*)d_in[4];
    const float* B2  = (const float*)d_in[5];
    const float* WrI = (const float*)d_in[6];
    const float* brI = (const float*)d_in[7];
    const float* WrT = (const float*)d_in[8];
    const float* brT = (const float*)d_in[9];
    float* out = (float*)d_out;

    const int E  = in_sizes[7];            // 4
    const int V  = in_sizes[6] / E;        // 32000
    const int BS = in_sizes[0];            // 4096 tokens

    dim3 grid(DDIM / NB, (BS + MT - 1) / MT);   // (32, 64)
    moe_emb_mma<<<grid, THREADS>>>(x, emb, A1, B1, A2, B2,
                                   WrI, brI, WrT, brT, out, V, BS);
}

// round 16
// speedup vs baseline: 1.4102x; 1.4102x over previous
#include <cuda_runtime.h>
#include <cuda_bf16.h>
#include <cstdint>

#define DDIM    4096
#define SEQ     512
#define SPLIT   32
#define SCALE   2.0f
#define MT      64       // tokens per block
#define NB      128      // d per block
#define THREADS 256
#define MAXTOK  4096
#define TRS     160      // transpose-tile row stride in bytes (40 floats)
#define TWB     2560     // per-warp transpose tile bytes (16 rows x TRS)

// device scratch (static allocation allowed)
__device__ __align__(16) __nv_bfloat16 g_coef[MAXTOK * 32];
__device__ int g_xi[MAXTOK];

__device__ __forceinline__ uint32_t cvta_s(const void* p) {
    return (uint32_t)__cvta_generic_to_shared(p);
}
__device__ __forceinline__ uint32_t bf2(float a, float b) {
    __nv_bfloat162 t = __floats2bfloat162_rn(a, b);
    return *reinterpret_cast<uint32_t*>(&t);
}
__device__ __forceinline__ void ldsm_x4(uint32_t& r0, uint32_t& r1, uint32_t& r2,
                                        uint32_t& r3, uint32_t addr) {
    asm volatile("ldmatrix.sync.aligned.m8n8.x4.shared.b16 {%0,%1,%2,%3}, [%4];"
                 : "=r"(r0), "=r"(r1), "=r"(r2), "=r"(r3) : "r"(addr));
}
__device__ __forceinline__ void ldsm_x2(uint32_t& r0, uint32_t& r1, uint32_t addr) {
    asm volatile("ldmatrix.sync.aligned.m8n8.x2.shared.b16 {%0,%1}, [%2];"
                 : "=r"(r0), "=r"(r1) : "r"(addr));
}
__device__ __forceinline__ void mma16816(float* d, const uint32_t* a, const uint32_t* b) {
    asm volatile(
        "mma.sync.aligned.m16n8k16.row.col.f32.bf16.bf16.f32 "
        "{%0,%1,%2,%3}, {%4,%5,%6,%7}, {%8,%9}, {%0,%1,%2,%3};"
        : "+f"(d[0]), "+f"(d[1]), "+f"(d[2]), "+f"(d[3])
        : "r"(a[0]), "r"(a[1]), "r"(a[2]), "r"(a[3]), "r"(b[0]), "r"(b[1]));
}

// ===== kernel 1: per-token bf16 coefficients + clamped indices =====
// 32 threads/token; thread s covers coef s (1 scattered A-gather each, max MLP).
__global__ void coef_kernel(const int* __restrict__ xg,
                            const float* __restrict__ A1, const float* __restrict__ A2,
                            const float* __restrict__ WrI, const float* __restrict__ brI,
                            const float* __restrict__ WrT, const float* __restrict__ brT,
                            int V, int n_tok)
{
    int idx = blockIdx.x * blockDim.x + threadIdx.x;
    int t = idx >> 5, s = idx & 31;
    if (t >= n_tok) return;

    int xi = xg[t];
    xi = (xi < 0) ? 0 : ((xi >= V) ? V - 1 : xi);
    if (s == 0) g_xi[t] = xi;

    bool img = ((t % SEQ) < SPLIT);
    const float* Wr = img ? WrI : WrT;
    const float* br = img ? brI : brT;
    float l0 = __ldg(Wr + xi) + __ldg(br + 0);
    float l1 = __ldg(Wr + (size_t)V + xi) + __ldg(br + 1);
    float w0 = 1.0f / (1.0f + __expf(l1 - l0));

    const float* A = (s < 16) ? A1 : A2;
    float w = ((s < 16) ? w0 : (1.0f - w0)) * SCALE;
    int j = s & 15;

    float v = w * __ldg(A + (size_t)j * V + xi);
    __nv_bfloat16 b = __float2bfloat16(v);
    *reinterpret_cast<__nv_bfloat16*>(
        reinterpret_cast<char*>(g_coef) + (size_t)t * 64 + s * 2) = b;
}

// ===== kernel 2: mma.sync delta GEMM + split-half transpose epilogue =====
__global__ __launch_bounds__(THREADS, 3)
void moe_emb_mma(const float* __restrict__ emb,
                 const float* __restrict__ B1, const float* __restrict__ B2,
                 float* __restrict__ out, int n_tok)
{
    // phase A: A tile @0 (64x80B = 5120), B tile @5120 (128x80B = 10240)
    // phase B: per-warp 16x160B transpose tiles (8 x 2560 = 20480)
    __shared__ __align__(16) char sm[20480];
    __shared__ int sx[MT];

    const int tid  = threadIdx.x;
    const int lane = tid & 31;
    const int w    = tid >> 5;
    const int t0   = blockIdx.y * MT;
    const int d0   = blockIdx.x * NB;

    char* smA = sm;
    char* smB = sm + 5120;

    // ---- stage A tile (coefs, coalesced from scratch) ----
    if (tid < 64) {
        int tr = t0 + tid; if (tr >= n_tok) tr = n_tok - 1;
        sx[tid] = g_xi[tr];
    }
    {
        int row = tid >> 2, c = tid & 3;
        int tr = t0 + row; if (tr >= n_tok) tr = n_tok - 1;
        uint4 v = *reinterpret_cast<const uint4*>(
            reinterpret_cast<const char*>(g_coef) + (size_t)tr * 64 + c * 16);
        *reinterpret_cast<uint4*>(smA + row * 80 + c * 16) = v;
    }
    // ---- stage B tile: row n = [B1[d0+n][0..15] | B2[d0+n][0..15]] as bf16 ----
    {
        int n = tid >> 1, hb = tid & 1;
        const float* src = hb ? B2 : B1;
        const float4* s4 = reinterpret_cast<const float4*>(src + (size_t)(d0 + n) * 16);
        float4 v0 = s4[0], v1 = s4[1], v2 = s4[2], v3 = s4[3];
        uint4 p0, p1;
        p0.x = bf2(v0.x, v0.y); p0.y = bf2(v0.z, v0.w);
        p0.z = bf2(v1.x, v1.y); p0.w = bf2(v1.z, v1.w);
        p1.x = bf2(v2.x, v2.y); p1.y = bf2(v2.z, v2.w);
        p1.z = bf2(v3.x, v3.y); p1.w = bf2(v3.z, v3.w);
        char* dst = smB + n * 80 + hb * 32;
        *reinterpret_cast<uint4*>(dst)      = p0;
        *reinterpret_cast<uint4*>(dst + 16) = p1;
    }
    __syncthreads();

    const uint32_t sAu = cvta_s(smA), sBu = cvta_s(smB);
    const int tgw = (w >> 2) * 32;     // warp token group (0/32)
    const int dw  = (w & 3) * 32;      // warp d group within block

    // ---- B fragments ----
    uint32_t bfr[4][2][2];
#pragma unroll
    for (int ni = 0; ni < 4; ++ni)
#pragma unroll
        for (int kt = 0; kt < 2; ++kt) {
            uint32_t addr = sBu + (uint32_t)(dw + ni * 8 + (lane & 7)) * 80
                          + (uint32_t)(kt * 16 + ((lane >> 3) & 1) * 8) * 2;
            ldsm_x2(bfr[ni][kt][0], bfr[ni][kt][1], addr);
        }
    // ---- A fragments, both m-halves (tiles die at the next syncthreads) ----
    const int asel = lane >> 3;
    const int arow_off = (asel & 1) * 8 + (lane & 7);
    const int acol_off = (asel >> 1) * 8;
    uint32_t a0[2][4], a1[2][4];
#pragma unroll
    for (int kt = 0; kt < 2; ++kt) {
        ldsm_x4(a0[kt][0], a0[kt][1], a0[kt][2], a0[kt][3],
                sAu + (uint32_t)(tgw + arow_off) * 80
                    + (uint32_t)(kt * 16 + acol_off) * 2);
        ldsm_x4(a1[kt][0], a1[kt][1], a1[kt][2], a1[kt][3],
                sAu + (uint32_t)(tgw + 16 + arow_off) * 80
                    + (uint32_t)(kt * 16 + acol_off) * 2);
    }

    const int brow = lane >> 3;          // 0..3
    const int dq   = lane & 7;           // 0..7
    const int dgl  = d0 + dw + dq * 4;   // this lane's global d

    // ---- half-0 base gathers (4 x LDG.128, streaming) ----
    float4 bs0[4];
#pragma unroll
    for (int it = 0; it < 4; ++it)
        bs0[it] = __ldcs(reinterpret_cast<const float4*>(
            emb + (size_t)sx[tgw + it * 4 + brow] * DDIM + dgl));

    __syncthreads();   // A/B tiles consumed; smem becomes transpose buffers
    char* tw = sm + w * TWB;             // 16 rows x TRS bytes

    const int srow  = lane >> 2;         // frag row 0..7
    const int scol2 = 2 * (lane & 3);

    // ================= half 0 (tokens tgw+0..15) =================
    {
        float acc[4][4];
#pragma unroll
        for (int ni = 0; ni < 4; ++ni) { acc[ni][0]=acc[ni][1]=acc[ni][2]=acc[ni][3]=0.f; }
#pragma unroll
        for (int kt = 0; kt < 2; ++kt)
#pragma unroll
            for (int ni = 0; ni < 4; ++ni)
                mma16816(acc[ni], a0[kt], bfr[ni][kt]);

        // prefetch half-1 base gathers while MMA results settle
        float4 bs1[4];
#pragma unroll
        for (int it = 0; it < 4; ++it)
            bs1[it] = __ldcs(reinterpret_cast<const float4*>(
                emb + (size_t)sx[tgw + 16 + it * 4 + brow] * DDIM + dgl));

#pragma unroll
        for (int ni = 0; ni < 4; ++ni)
#pragma unroll
            for (int h = 0; h < 2; ++h)
                *reinterpret_cast<float2*>(tw + (h * 8 + srow) * TRS
                                              + (ni * 8 + scol2) * 4) =
                    make_float2(acc[ni][2 * h], acc[ni][2 * h + 1]);
        __syncwarp();

#pragma unroll
        for (int it = 0; it < 4; ++it) {
            int rt = it * 4 + brow;
            float4 dl = *reinterpret_cast<const float4*>(tw + rt * TRS + dq * 16);
            float4 o = bs0[it];
            o.x += dl.x; o.y += dl.y; o.z += dl.z; o.w += dl.w;
            int tk = tgw + rt;
            if (t0 + tk < n_tok)
                __stcs(reinterpret_cast<float4*>(out + (size_t)(t0 + tk) * DDIM + dgl), o);
        }
        __syncwarp();

        // ================= half 1 (tokens tgw+16..31) =================
        float acc1[4][4];
#pragma unroll
        for (int ni = 0; ni < 4; ++ni) { acc1[ni][0]=acc1[ni][1]=acc1[ni][2]=acc1[ni][3]=0.f; }
#pragma unroll
        for (int kt = 0; kt < 2; ++kt)
#pragma unroll
            for (int ni = 0; ni < 4; ++ni)
                mma16816(acc1[ni], a1[kt], bfr[ni][kt]);

#pragma unroll
        for (int ni = 0; ni < 4; ++ni)
#pragma unroll
            for (int h = 0; h < 2; ++h)
                *reinterpret_cast<float2*>(tw + (h * 8 + srow) * TRS
                                              + (ni * 8 + scol2) * 4) =
                    make_float2(acc1[ni][2 * h], acc1[ni][2 * h + 1]);
        __syncwarp();

#pragma unroll
        for (int it = 0; it < 4; ++it) {
            int rt = it * 4 + brow;
            float4 dl = *reinterpret_cast<const float4*>(tw + rt * TRS + dq * 16);
            float4 o = bs1[it];
            o.x += dl.x; o.y += dl.y; o.z += dl.z; o.w += dl.w;
            int tk = tgw + 16 + rt;
            if (t0 + tk < n_tok)
                __stcs(reinterpret_cast<float4*>(out + (size_t)(t0 + tk) * DDIM + dgl), o);
        }
    }
}

extern "C" void kernel_launch(void* const* d_in, const int* in_sizes, int n_in,
                              void* d_out, int out_size) {
    const int*   x   = (const int*)d_in[0];
    const float* emb = (const float*)d_in[1];
    const float* A1  = (const float*)d_in[2];
    const float* B1  = (const float*)d_in[3];
    const float* A2  = (const float*)d_in[4];
    const float* B2  = (const float*)d_in[5];
    const float* WrI = (const float*)d_in[6];
    const float* brI = (const float*)d_in[7];
    const float* WrT = (const float*)d_in[8];
    const float* brT = (const float*)d_in[9];
    float* out = (float*)d_out;

    const int E  = in_sizes[7];            // 4
    const int V  = in_sizes[6] / E;        // 32000
    const int BS = in_sizes[0];            // 4096 tokens

    int c_threads = 256;
    int c_blocks  = (BS * 32 + c_threads - 1) / c_threads;  // 512
    coef_kernel<<<c_blocks, c_threads>>>(x, A1, A2, WrI, brI, WrT, brT, V, BS);

    dim3 grid(DDIM / NB, (BS + MT - 1) / MT);   // (32, 64)
    moe_emb_mma<<<grid, THREADS>>>(emb, B1, B2, out, BS);
}